// round 15
// baseline (speedup 1.0000x reference)
#include <cuda_runtime.h>
#include <cuda_bf16.h>
#include <cstdint>

// ContinuousEmbedding: out[b,f,:] = sum_k weight[k,:] / (|idx(x[b,f]) - k| + 1)
// = 64x64 table T (16 KB = 1024 float4) indexed by bucket.
//
// R15 = R12 (champion, 28.70us) with ONE change: stores use the default
// eviction policy instead of .cs (evict-first). Final untested knob on the
// write path; everything else byte-identical to R12.

#define NUM_BINS 63
#define KDIM 64          // NUM_BINS + 1
#define EMB_DIM 64
#define NBUILD 8         // builder blocks: 8 x 128 float4 entries

__device__ float g_table[KDIM * EMB_DIM];   // 4096 floats = 1024 float4
__device__ int   g_ready;                   // builders done (0..NBUILD)
__device__ int   g_done;                    // blocks finished (for reset)

__global__ void __launch_bounds__(256, 5)
embed_fused(const float* __restrict__ x,
            const float* __restrict__ low,     // [64]; low[0]=-inf, bins=low[1..]
            const float* __restrict__ weight,  // [64*64]
            float4* __restrict__ out,
            int n_rows)
{
    const int tid = threadIdx.x;
    const int bid = blockIdx.x;

    // ---- phase 1a: builder blocks compute 128 table entries each ----------
    if (bid < NBUILD) {
        __shared__ float srecip[KDIM];
        if (tid < KDIM) srecip[tid] = 1.0f / (float)(tid + 1);
        __syncthreads();
        if (tid < 128) {
            const int e = bid * 128 + tid;     // float4 entry 0..1023
            const int r = e >> 4;              // 0..63
            const int c = e & 15;              // 0..15
            const float4* w4 = reinterpret_cast<const float4*>(weight);
            float4 acc = make_float4(0.f, 0.f, 0.f, 0.f);
#pragma unroll 16
            for (int k = 0; k < KDIM; ++k) {
                int d = r - k; if (d < 0) d = -d;
                const float  s = srecip[d];
                const float4 w = __ldg(w4 + k * 16 + c);
                acc.x = fmaf(w.x, s, acc.x);
                acc.y = fmaf(w.y, s, acc.y);
                acc.z = fmaf(w.z, s, acc.z);
                acc.w = fmaf(w.w, s, acc.w);
            }
            reinterpret_cast<float4*>(g_table)[e] = acc;
        }
        __threadfence();                       // table writes visible (gpu scope)
        __syncthreads();
        if (tid == 0) atomicAdd(&g_ready, 1);
    }

    // ---- phase 1b (all blocks): bucket index, overlapped with build -------
    const int lane = tid & 31;
    const int warp = tid >> 5;
    const int half = lane >> 4;        // row-within-pair
    const int part = lane & 15;        // float4 slot within a 64-float row
    const int base = (bid * 8 + warp) * 32;
    const bool active = (base < n_rows);

    // g = #{ j : bins[j] < x }: arithmetic guess (bins ~ linspace(-3.1,3.1))
    // then EXACT fixup against the real bin values (low[g] == bins[g-1]).
    int g = 0;
    if (active && base + lane < n_rows) {
        const float xv = __ldg(x + base + lane);
        g = (int)floorf((xv + 3.1f) * 10.0f) + 1;
        g = max(0, min(NUM_BINS, g));
        while (g > 0 && !(xv > __ldg(low + g))) --g;
        while (g < NUM_BINS && (xv > __ldg(low + g + 1))) ++g;
    }

    // ---- phase 2: wait for the table (backoff spin) ------------------------
    if (tid == 0) {
        int r;
        asm volatile("ld.global.acquire.gpu.b32 %0, [%1];"
                     : "=r"(r) : "l"(&g_ready) : "memory");
        while (r < NBUILD) {
            __nanosleep(256);
            asm volatile("ld.global.acquire.gpu.b32 %0, [%1];"
                         : "=r"(r) : "l"(&g_ready) : "memory");
        }
    }
    __syncthreads();

    // ---- phase 3: fan-out (default eviction policy stores) -----------------
    if (active) {
        const float4* table = reinterpret_cast<const float4*>(g_table);
        const bool full = (base + 32 <= n_rows);   // uniform within warp
#pragma unroll
        for (int h = 0; h < 2; ++h) {
            int    idxs[8];
            float4 v[8];
#pragma unroll
            for (int j = 0; j < 8; ++j)
                idxs[j] = __shfl_sync(0xffffffffu, g, (h * 8 + j) * 2 + half);
#pragma unroll
            for (int j = 0; j < 8; ++j)
                v[j] = __ldg(&table[(idxs[j] << 4) + part]);
            if (full) {
#pragma unroll
                for (int j = 0; j < 8; ++j)
                    out[(size_t)(base + (h * 8 + j) * 2) * 16 + lane] = v[j];
            } else {
#pragma unroll
                for (int j = 0; j < 8; ++j) {
                    const int r = base + (h * 8 + j) * 2 + half;
                    if (r < n_rows)
                        out[(size_t)r * 16 + part] = v[j];
                }
            }
        }
    }

    // ---- phase 4: self-reset so every launch is identical ------------------
    __syncthreads();
    if (tid == 0) {
        const int prev = atomicAdd(&g_done, 1);
        if (prev == (int)gridDim.x - 1) {      // last block: reset protocol
            atomicExch(&g_done, 0);
            atomicExch(&g_ready, 0);
        }
    }
}

extern "C" void kernel_launch(void* const* d_in, const int* in_sizes, int n_in,
                              void* d_out, int out_size) {
    const float* x      = (const float*)d_in[0];   // [B*F]
    const float* low    = (const float*)d_in[1];   // [64]
    // d_in[2] = high [64] (redundant with low for the bucket computation)
    const float* weight = (const float*)d_in[3];   // [64*64]

    float4* out = (float4*)d_out;
    const int n_rows = out_size / EMB_DIM;         // 524288

    // One-shot grid: 8 warps x 32 rows per block. At least NBUILD blocks.
    int blocks = (n_rows + 255) / 256;             // 2048 for the real shape
    if (blocks < NBUILD) blocks = NBUILD;

    embed_fused<<<blocks, 256>>>(x, low, weight, out, n_rows);
}

// round 16
// speedup vs baseline: 1.1670x; 1.1670x over previous
#include <cuda_runtime.h>
#include <cuda_bf16.h>
#include <cstdint>

// ContinuousEmbedding: out[b,f,:] = sum_k weight[k,:] / (|idx(x[b,f]) - k| + 1)
// = 64x64 table T (16 KB = 1024 float4) indexed by bucket.
//
// FINAL (= R12, champion at 28.70us): single kernel. Blocks 0..7 build the
// table (128 float4 entries each); all blocks overlap their x-load + bucket
// fixup with the build, then backoff-spin on an acquire-loaded ready counter
// before the gather. Fan-out: 8-deep register-batched
// {shfl -> LDG.128 table (L1) -> STG.128.cs}, launch_bounds(256,5).
// Self-resetting protocol -> identical work every launch (graph-safe).
//
// Search summary (15 rounds): store mechanism (STG.128/.256, TMA bulk x2,
// smem-staged), gather source (LDS/LDG), warp structure, occupancy 23-76%,
// schedule (one-shot/persistent/prefetch), eviction policy (.cs/default) all
// explored; kernel is pinned at the L1tex/L2 write-wavefront floor for the
// 134 MB output. .cs eviction worth ~3.5us; everything else invariant.

#define NUM_BINS 63
#define KDIM 64          // NUM_BINS + 1
#define EMB_DIM 64
#define NBUILD 8         // builder blocks: 8 x 128 float4 entries

__device__ float g_table[KDIM * EMB_DIM];   // 4096 floats = 1024 float4
__device__ int   g_ready;                   // builders done (0..NBUILD)
__device__ int   g_done;                    // blocks finished (for reset)

__global__ void __launch_bounds__(256, 5)
embed_fused(const float* __restrict__ x,
            const float* __restrict__ low,     // [64]; low[0]=-inf, bins=low[1..]
            const float* __restrict__ weight,  // [64*64]
            float4* __restrict__ out,
            int n_rows)
{
    const int tid = threadIdx.x;
    const int bid = blockIdx.x;

    // ---- phase 1a: builder blocks compute 128 table entries each ----------
    if (bid < NBUILD) {
        __shared__ float srecip[KDIM];
        if (tid < KDIM) srecip[tid] = 1.0f / (float)(tid + 1);
        __syncthreads();
        if (tid < 128) {
            const int e = bid * 128 + tid;     // float4 entry 0..1023
            const int r = e >> 4;              // 0..63
            const int c = e & 15;              // 0..15
            const float4* w4 = reinterpret_cast<const float4*>(weight);
            float4 acc = make_float4(0.f, 0.f, 0.f, 0.f);
#pragma unroll 16
            for (int k = 0; k < KDIM; ++k) {
                int d = r - k; if (d < 0) d = -d;
                const float  s = srecip[d];
                const float4 w = __ldg(w4 + k * 16 + c);
                acc.x = fmaf(w.x, s, acc.x);
                acc.y = fmaf(w.y, s, acc.y);
                acc.z = fmaf(w.z, s, acc.z);
                acc.w = fmaf(w.w, s, acc.w);
            }
            reinterpret_cast<float4*>(g_table)[e] = acc;
        }
        __threadfence();                       // table writes visible (gpu scope)
        __syncthreads();
        if (tid == 0) atomicAdd(&g_ready, 1);
    }

    // ---- phase 1b (all blocks): bucket index, overlapped with build -------
    const int lane = tid & 31;
    const int warp = tid >> 5;
    const int half = lane >> 4;        // row-within-pair
    const int part = lane & 15;        // float4 slot within a 64-float row
    const int base = (bid * 8 + warp) * 32;
    const bool active = (base < n_rows);

    // g = #{ j : bins[j] < x }: arithmetic guess (bins ~ linspace(-3.1,3.1))
    // then EXACT fixup against the real bin values (low[g] == bins[g-1]).
    int g = 0;
    if (active && base + lane < n_rows) {
        const float xv = __ldg(x + base + lane);
        g = (int)floorf((xv + 3.1f) * 10.0f) + 1;
        g = max(0, min(NUM_BINS, g));
        while (g > 0 && !(xv > __ldg(low + g))) --g;
        while (g < NUM_BINS && (xv > __ldg(low + g + 1))) ++g;
    }

    // ---- phase 2: wait for the table (backoff spin, low L2 pressure) ------
    if (tid == 0) {
        int r;
        asm volatile("ld.global.acquire.gpu.b32 %0, [%1];"
                     : "=r"(r) : "l"(&g_ready) : "memory");
        while (r < NBUILD) {
            __nanosleep(256);
            asm volatile("ld.global.acquire.gpu.b32 %0, [%1];"
                         : "=r"(r) : "l"(&g_ready) : "memory");
        }
    }
    __syncthreads();

    // ---- phase 3: fan-out (measured-floor shape, .cs streaming stores) ----
    if (active) {
        const float4* table = reinterpret_cast<const float4*>(g_table);
        const bool full = (base + 32 <= n_rows);   // uniform within warp
#pragma unroll
        for (int h = 0; h < 2; ++h) {
            int    idxs[8];
            float4 v[8];
#pragma unroll
            for (int j = 0; j < 8; ++j)
                idxs[j] = __shfl_sync(0xffffffffu, g, (h * 8 + j) * 2 + half);
#pragma unroll
            for (int j = 0; j < 8; ++j)
                v[j] = __ldg(&table[(idxs[j] << 4) + part]);
            if (full) {
#pragma unroll
                for (int j = 0; j < 8; ++j)
                    __stcs(&out[(size_t)(base + (h * 8 + j) * 2) * 16 + lane], v[j]);
            } else {
#pragma unroll
                for (int j = 0; j < 8; ++j) {
                    const int r = base + (h * 8 + j) * 2 + half;
                    if (r < n_rows)
                        __stcs(&out[(size_t)r * 16 + part], v[j]);
                }
            }
        }
    }

    // ---- phase 4: self-reset so every launch is identical ------------------
    __syncthreads();
    if (tid == 0) {
        const int prev = atomicAdd(&g_done, 1);
        if (prev == (int)gridDim.x - 1) {      // last block: reset protocol
            atomicExch(&g_done, 0);
            atomicExch(&g_ready, 0);
        }
    }
}

extern "C" void kernel_launch(void* const* d_in, const int* in_sizes, int n_in,
                              void* d_out, int out_size) {
    const float* x      = (const float*)d_in[0];   // [B*F]
    const float* low    = (const float*)d_in[1];   // [64]
    // d_in[2] = high [64] (redundant with low for the bucket computation)
    const float* weight = (const float*)d_in[3];   // [64*64]

    float4* out = (float4*)d_out;
    const int n_rows = out_size / EMB_DIM;         // 524288

    // One-shot grid: 8 warps x 32 rows per block. At least NBUILD blocks.
    int blocks = (n_rows + 255) / 256;             // 2048 for the real shape
    if (blocks < NBUILD) blocks = NBUILD;

    embed_fused<<<blocks, 256>>>(x, low, weight, out, n_rows);
}

// round 17
// speedup vs baseline: 1.2447x; 1.0665x over previous
#include <cuda_runtime.h>
#include <cuda_bf16.h>
#include <cstdint>

// ContinuousEmbedding: out[b,f,:] = sum_k weight[k,:] / (|idx(x[b,f]) - k| + 1)
// = 64x64 table T (16 KB = 1024 float4) indexed by bucket.
//
// R17 = champion (R12, 28.70us) with the build critical path shortened:
// builders stage weight via one cooperative LDG wave into shared (removes the
// 64-deep per-thread LDG chain), and NBUILD 8 -> 16 (64 entries per builder).
// Fan-out, grid, spin, reset protocol byte-identical to the champion.

#define NUM_BINS 63
#define KDIM 64          // NUM_BINS + 1
#define EMB_DIM 64
#define NBUILD 16        // builder blocks: 16 x 64 float4 entries

__device__ float g_table[KDIM * EMB_DIM];   // 4096 floats = 1024 float4
__device__ int   g_ready;                   // builders done (0..NBUILD)
__device__ int   g_done;                    // blocks finished (for reset)

__global__ void __launch_bounds__(256, 5)
embed_fused(const float* __restrict__ x,
            const float* __restrict__ low,     // [64]; low[0]=-inf, bins=low[1..]
            const float* __restrict__ weight,  // [64*64]
            float4* __restrict__ out,
            int n_rows)
{
    const int tid = threadIdx.x;
    const int bid = blockIdx.x;

    // ---- phase 1a: builder blocks compute 64 table entries each -----------
    if (bid < NBUILD) {
        __shared__ float4 sw[KDIM * 16];       // 16 KB staged weight
        __shared__ float  srecip[KDIM];
        const float4* w4 = reinterpret_cast<const float4*>(weight);
        // one cooperative LDG wave: 4 float4 per thread, full MLP
#pragma unroll
        for (int i = 0; i < 4; ++i)
            sw[tid + 256 * i] = __ldg(w4 + tid + 256 * i);
        if (tid < KDIM) srecip[tid] = 1.0f / (float)(tid + 1);
        __syncthreads();

        if (tid < 64) {
            const int e = bid * 64 + tid;      // float4 entry 0..1023
            const int r = e >> 4;              // 0..63
            const int c = e & 15;              // 0..15
            float4 acc = make_float4(0.f, 0.f, 0.f, 0.f);
#pragma unroll 16
            for (int k = 0; k < KDIM; ++k) {
                int d = r - k; if (d < 0) d = -d;
                const float  s = srecip[d];
                const float4 w = sw[k * 16 + c];
                acc.x = fmaf(w.x, s, acc.x);
                acc.y = fmaf(w.y, s, acc.y);
                acc.z = fmaf(w.z, s, acc.z);
                acc.w = fmaf(w.w, s, acc.w);
            }
            reinterpret_cast<float4*>(g_table)[e] = acc;
        }
        __threadfence();                       // table writes visible (gpu scope)
        __syncthreads();
        if (tid == 0) atomicAdd(&g_ready, 1);
    }

    // ---- phase 1b (all blocks): bucket index, overlapped with build -------
    const int lane = tid & 31;
    const int warp = tid >> 5;
    const int half = lane >> 4;        // row-within-pair
    const int part = lane & 15;        // float4 slot within a 64-float row
    const int base = (bid * 8 + warp) * 32;
    const bool active = (base < n_rows);

    // g = #{ j : bins[j] < x }: arithmetic guess (bins ~ linspace(-3.1,3.1))
    // then EXACT fixup against the real bin values (low[g] == bins[g-1]).
    int g = 0;
    if (active && base + lane < n_rows) {
        const float xv = __ldg(x + base + lane);
        g = (int)floorf((xv + 3.1f) * 10.0f) + 1;
        g = max(0, min(NUM_BINS, g));
        while (g > 0 && !(xv > __ldg(low + g))) --g;
        while (g < NUM_BINS && (xv > __ldg(low + g + 1))) ++g;
    }

    // ---- phase 2: wait for the table (backoff spin, low L2 pressure) ------
    if (tid == 0) {
        int r;
        asm volatile("ld.global.acquire.gpu.b32 %0, [%1];"
                     : "=r"(r) : "l"(&g_ready) : "memory");
        while (r < NBUILD) {
            __nanosleep(256);
            asm volatile("ld.global.acquire.gpu.b32 %0, [%1];"
                         : "=r"(r) : "l"(&g_ready) : "memory");
        }
    }
    __syncthreads();

    // ---- phase 3: fan-out (measured-floor shape, .cs streaming stores) ----
    if (active) {
        const float4* table = reinterpret_cast<const float4*>(g_table);
        const bool full = (base + 32 <= n_rows);   // uniform within warp
#pragma unroll
        for (int h = 0; h < 2; ++h) {
            int    idxs[8];
            float4 v[8];
#pragma unroll
            for (int j = 0; j < 8; ++j)
                idxs[j] = __shfl_sync(0xffffffffu, g, (h * 8 + j) * 2 + half);
#pragma unroll
            for (int j = 0; j < 8; ++j)
                v[j] = __ldg(&table[(idxs[j] << 4) + part]);
            if (full) {
#pragma unroll
                for (int j = 0; j < 8; ++j)
                    __stcs(&out[(size_t)(base + (h * 8 + j) * 2) * 16 + lane], v[j]);
            } else {
#pragma unroll
                for (int j = 0; j < 8; ++j) {
                    const int r = base + (h * 8 + j) * 2 + half;
                    if (r < n_rows)
                        __stcs(&out[(size_t)r * 16 + part], v[j]);
                }
            }
        }
    }

    // ---- phase 4: self-reset so every launch is identical ------------------
    __syncthreads();
    if (tid == 0) {
        const int prev = atomicAdd(&g_done, 1);
        if (prev == (int)gridDim.x - 1) {      // last block: reset protocol
            atomicExch(&g_done, 0);
            atomicExch(&g_ready, 0);
        }
    }
}

extern "C" void kernel_launch(void* const* d_in, const int* in_sizes, int n_in,
                              void* d_out, int out_size) {
    const float* x      = (const float*)d_in[0];   // [B*F]
    const float* low    = (const float*)d_in[1];   // [64]
    // d_in[2] = high [64] (redundant with low for the bucket computation)
    const float* weight = (const float*)d_in[3];   // [64*64]

    float4* out = (float4*)d_out;
    const int n_rows = out_size / EMB_DIM;         // 524288

    // One-shot grid: 8 warps x 32 rows per block. At least NBUILD blocks.
    int blocks = (n_rows + 255) / 256;             // 2048 for the real shape
    if (blocks < NBUILD) blocks = NBUILD;

    embed_fused<<<blocks, 256>>>(x, low, weight, out, n_rows);
}